// round 14
// baseline (speedup 1.0000x reference)
#include <cuda_runtime.h>

#define N 128
#define BATCH 32
#define NITERS 500
#define RHO 0.1f
#define SIGMA 1e-6f
#define RELAX 1.6f
#define ALPHA 0.5f
#define DELTA 10.0f

typedef unsigned long long ull;

union F2U { ull u; float2 f; };
__device__ __forceinline__ ull pack2(float x, float y) { F2U u; u.f = make_float2(x, y); return u.u; }
__device__ __forceinline__ ull fma2(ull a, ull b, ull c) {
    ull d; asm("fma.rn.f32x2 %0, %1, %2, %3;" : "=l"(d) : "l"(a), "l"(b), "l"(c)); return d;
}
__device__ __forceinline__ ull add2(ull a, ull b) {
    ull d; asm("add.rn.f32x2 %0, %1, %2;" : "=l"(d) : "l"(a), "l"(b)); return d;
}
__device__ __forceinline__ ull mul2(ull a, ull b) {
    ull d; asm("mul.rn.f32x2 %0, %1, %2;" : "=l"(d) : "l"(a), "l"(b)); return d;
}

// Interleaved dd layout: half0 chunk m -> floats 8m+0..3, half1 chunk m -> 8m+4..7.
// A warp's two broadcast LDS.128 addresses are 16B apart in one 32B window
// (disjoint banks) -> ONE shared wavefront per LDS instead of two.
__device__ __forceinline__ int dd_slot(int j) {
    return (j < 64) ? (8 * (j >> 2) + (j & 3))
                    : (8 * ((j - 64) >> 2) + 4 + ((j - 64) & 3));
}

// One fused kernel, 288 threads:
//   warps 0-7 : row j = w*16+(l&15), half hf = l>>4; W half-row in registers
//               from Gauss-Jordan straight through the ADMM loop.
//   warp 8    : scalar equality row (ATOMS-based reduction).
__global__ void __launch_bounds__(288, 1)
mvo_kernel(const float* __restrict__ X, const float* __restrict__ V,
           const float* __restrict__ beta, const float* __restrict__ thE,
           const float* __restrict__ thD, const float* __restrict__ lg1,
           const float* __restrict__ lg2, const float* __restrict__ bvec,
           const float* __restrict__ hvec, float* __restrict__ out) {
    __shared__ __align__(16) ull rowbuf[2][64];
    __shared__ __align__(16) float sddI[2][N];      // interleaved dd, double buffered
    __shared__ __align__(16) float sqI[N];          // q permuted into dd_slot order
    __shared__ float red8[8];
    __shared__ float sQ1;
    __shared__ float c2buf[2];
    __shared__ float accum[2];
    __shared__ __align__(16) float sx[N];

    const int tid = threadIdx.x;
    const int b = blockIdx.x;
    const int w = tid >> 5, l = tid & 31;
    const bool rowt = (tid < 256);
    const int j = (w & 7) * 16 + (l & 15);
    const int hf = l >> 4;

    if (tid < 128) sx[tid] = X[b * N + tid];
    if (tid == 0) {
        c2buf[0] = 0.f; c2buf[1] = 0.f;
        accum[0] = 0.f; accum[1] = 0.f;
    }
    __syncthreads();

    // ---------- per-row constants + y_pred ----------
    float yp2 = 0.f, pt2 = 0.f, up1 = 0.f;
    ull rr[32];
    if (rowt) {
        float acc = 0.f;
        {
            const float* xp = sx + hf * 64;
            const float* bp = beta + (hf * 64) * N + j;
#pragma unroll 8
            for (int k = 0; k < 64; k++) acc = fmaf(xp[k], bp[k * N], acc);
        }
        float yp = acc + __shfl_xor_sync(0xffffffffu, acc, 16);
        if (hf == 0) out[BATCH * N + b * N + j] = yp;
        yp2 = 2.0f * yp;
        const float g1v = exp10f(lg1[0]);
        const float ev  = 1.0f / (1.0f + expf(-thE[j]));
        pt2 = 2.0f * (ALPHA * g1v * ev);
        up1 = hvec[j];

        const float g2 = exp10f(lg2[0]);
        const float sg = 1.0f / (1.0f + expf(-thD[j]));
        const float dg = 2.0f * (1.0f - ALPHA) * g2 * sg * sg + 3.0f * RHO + SIGMA;
        const float2* vrow = (const float2*)(V + j * N + hf * 64);
#pragma unroll
        for (int m = 0; m < 32; m++) {
            float2 v = vrow[m];
            float a = fmaf(2.0f * DELTA, v.x, 2.0f * RHO);
            float c = fmaf(2.0f * DELTA, v.y, 2.0f * RHO);
            int gc = hf * 64 + 2 * m;
            if (gc == j)     a += dg;
            if (gc + 1 == j) c += dg;
            rr[m] = pack2(a, c);
        }
    }

    // ---------- 128 Gauss-Jordan pivots (1 barrier each) ----------
#pragma unroll
    for (int k = 0; k < N; k++) {
        ull* buf = rowbuf[k & 1];
        if (rowt && j == k) {
            ulonglong2* buf2 = (ulonglong2*)buf;
#pragma unroll
            for (int m = 0; m < 16; m++)
                buf2[hf * 16 + m] = make_ulonglong2(rr[2 * m], rr[2 * m + 1]);
        }
        __syncthreads();
        if (rowt) {
            const float* bf = (const float*)buf;
            const float d = 1.0f / bf[k];
            const int mm = (k & 63) >> 1;
            F2U u; u.u = rr[mm];
            float fown = (k & 1) ? u.f.y : u.f.x;
            float f = __shfl_sync(0xffffffffu, fown, (l & 15) | ((k >> 6) << 4));
            const ulonglong2* bh = (const ulonglong2*)(buf + hf * 32);
            if (j == k) {
                ull d2 = pack2(d, d);
#pragma unroll
                for (int m = 0; m < 32; m++) rr[m] = mul2(rr[m], d2);
                if (hf == (k >> 6)) {
                    F2U t; t.u = rr[mm];
                    if (k & 1) t.f.y = d; else t.f.x = d;
                    rr[mm] = t.u;
                }
            } else {
                float fd = f * d;
                ull nf2 = pack2(-fd, -fd);
#pragma unroll
                for (int m = 0; m < 16; m++) {
                    ulonglong2 bb = bh[m];
                    rr[2 * m]     = fma2(nf2, bb.x, rr[2 * m]);
                    rr[2 * m + 1] = fma2(nf2, bb.y, rr[2 * m + 1]);
                }
                if (hf == (k >> 6)) {
                    F2U t; t.u = rr[mm];
                    if (k & 1) t.f.y = -fd; else t.f.x = -fd;
                    rr[mm] = t.u;
                }
            }
        }
    }

    // ---------- q = W@1, Q1 ----------
    float qj = 0.f;
    const int slot = dd_slot(j);
    if (rowt) {
        ull s0 = 0, s1 = 0, s2 = 0, s3 = 0;
#pragma unroll
        for (int m = 0; m < 32; m += 4) {
            s0 = add2(s0, rr[m]);     s1 = add2(s1, rr[m + 1]);
            s2 = add2(s2, rr[m + 2]); s3 = add2(s3, rr[m + 3]);
        }
        F2U ts; ts.u = add2(add2(s0, s1), add2(s2, s3));
        float qh = ts.f.x + ts.f.y;
        qj = qh + __shfl_xor_sync(0xffffffffu, qh, 16);
        if (hf == 0) sqI[slot] = qj;
        float r = qj;
        r += __shfl_xor_sync(0xffffffffu, r, 8);
        r += __shfl_xor_sync(0xffffffffu, r, 4);
        r += __shfl_xor_sync(0xffffffffu, r, 2);
        r += __shfl_xor_sync(0xffffffffu, r, 1);
        if (l == 0) red8[w] = r;
    }
    __syncthreads();
    if (tid == 0) {
        float t = 0.f;
#pragma unroll
        for (int i = 0; i < 8; i++) t += red8[i];
        sQ1 = t;
    }

    const float omr = 1.0f - RELAX;
    const float half_inv_rs = 0.5f / (RHO + SIGMA);

    // initial ddl (x=z=y=0): ddl = yp2, in interleaved slot
    if (rowt && hf == 0) sddI[0][slot] = yp2;
    __syncthreads();   // covers sQ1 + initial dd

    // ---------- 500-iteration ADMM ----------
    if (rowt) {
        const ull HALF2 = pack2(0.5f, -0.5f);
        const ull R2v   = pack2(RELAX, RELAX);
        const ull mR2   = pack2(-RELAX, -RELAX);
        const ull OMR2  = pack2(omr, omr);

        ull Xp = 0ull;                 // (x1, x2)
        ull V23 = 0ull;                // (v2, v3)
        float v1 = 0.f, z1 = 0.f;
        float ddl = yp2, s = -pt2;
        bool first = true;

#pragma unroll 2
        for (int it = 0; it < NITERS; it++) {
            const int p = it & 1;
            if (!first && hf == 0) sddI[p][slot] = ddl;
            first = false;
            __syncthreads();
            const float c2 = c2buf[p];

            // interleaved half-row matvec: 16 LDS.128 (1 wavefront each) + 32 fma2
            const ulonglong2* dds = (const ulonglong2*)sddI[p];
            ull a0 = 0ull, a1 = 0ull, a2 = 0ull, a3 = 0ull;
#pragma unroll
            for (int m = 0; m < 8; m++) {
                ulonglong2 d0 = dds[4 * m + hf];
                ulonglong2 d1 = dds[4 * m + 2 + hf];
                a0 = fma2(rr[4 * m + 0], d0.x, a0);
                a1 = fma2(rr[4 * m + 1], d0.y, a1);
                a2 = fma2(rr[4 * m + 2], d1.x, a2);
                a3 = fma2(rr[4 * m + 3], d1.y, a3);
            }
            F2U acc; acc.u = add2(add2(a0, a1), add2(a2, a3));
            float th = acc.f.x + acc.f.y;
            float t = fmaf(c2, qj, th + __shfl_xor_sync(0xffffffffu, th, 16));

            // ---- slim epilogue (v-state form, f32x2-packed) ----
            float hsu = s * half_inv_rs;
            ull XT = fma2(HALF2, pack2(t, t), pack2(hsu, hsu));     // (xt1, xt2)
            Xp = fma2(R2v, XT, mul2(OMR2, Xp));                     // (x1, x2)

            float a1r = fmaf(-RELAX, z1, v1);
            v1 = fmaf(-RELAX, t, a1r);
            z1 = fminf(v1, up1);
            float u1 = fmaf(2.0f, z1, -v1);

            F2U vo; vo.u = V23;
            float a2r = fmaxf(vo.f.x, omr * vo.f.x);
            float a3r = fmaxf(vo.f.y, omr * vo.f.y);
            V23 = fma2(mR2, XT, pack2(a2r, a3r));
            F2U vn; vn.u = V23;
            float av2 = fabsf(vn.f.x);
            float av3 = fabsf(vn.f.y);

            F2U xu; xu.u = Xp;
            float dx  = xu.f.x - xu.f.y;
            float sxx = xu.f.x + xu.f.y;
            ddl = fmaf(SIGMA, dx, yp2);
            ddl = fmaf(-2.0f * RHO, u1, ddl);
            ddl = fmaf(RHO, av2, ddl);
            ddl = fmaf(-RHO, av3, ddl);
            s = fmaf(SIGMA, sxx, -pt2);
            s = fmaf(RHO, av2, s);
            s = fmaf(RHO, av3, s);
        }
        if (hf == 0) {
            F2U xu; xu.u = Xp;
            out[b * N + j] = xu.f.x - xu.f.y;
        }
    } else {
        // warp 8: scalar equality row, ATOMS reduction (shorter straggler path)
        float4 qa = ((const float4*)sqI)[l];    // q in dd_slot permutation
        float Q1v = sQ1;
        float b0 = bvec[0];
        float c2 = 0.f, Y0 = 0.f, z0 = 0.f;
#pragma unroll 2
        for (int it = 0; it < NITERS; it++) {
            const int p = it & 1;
            __syncthreads();
            float4 da = ((const float4*)sddI[p])[l];
            float partial = (qa.x * da.x + qa.y * da.y)
                          + (qa.z * da.z + qa.w * da.w);
            atomicAdd(&accum[p], partial);
            __syncwarp();
            if (l == 0) {
                float r = accum[p];
                accum[p] = 0.f;                 // re-zero for iteration it+2
                float zt0 = fmaf(c2, Q1v, r);
                float zr0 = fmaf(omr, z0, RELAX * zt0);
                Y0 = Y0 + zr0 - b0;
                z0 = b0;
                c2 = 2.0f * RHO * (b0 - Y0);
                c2buf[p ^ 1] = c2;
            }
        }
    }
}

// ---------------- launcher ----------------
extern "C" void kernel_launch(void* const* d_in, const int* in_sizes, int n_in,
                              void* d_out, int out_size) {
    const float* X    = (const float*)d_in[0];
    const float* V    = (const float*)d_in[1];
    const float* beta = (const float*)d_in[2];
    const float* thE  = (const float*)d_in[3];
    const float* thD  = (const float*)d_in[4];
    const float* lg1  = (const float*)d_in[5];
    const float* lg2  = (const float*)d_in[6];
    const float* bvec = (const float*)d_in[8];
    const float* hvec = (const float*)d_in[10];
    float* out = (float*)d_out;

    mvo_kernel<<<BATCH, 288>>>(X, V, beta, thE, thD, lg1, lg2, bvec, hvec, out);
}

// round 15
// speedup vs baseline: 4.5635x; 4.5635x over previous
#include <cuda_runtime.h>

#define N 128
#define BATCH 32
#define NITERS 500
#define RHO 0.1f
#define SIGMA 1e-6f
#define RELAX 1.6f
#define ALPHA 0.5f
#define DELTA 10.0f

typedef unsigned long long ull;

union F2U { ull u; float2 f; };
__device__ __forceinline__ ull pack2(float x, float y) { F2U u; u.f = make_float2(x, y); return u.u; }
__device__ __forceinline__ ull fma2(ull a, ull b, ull c) {
    ull d; asm("fma.rn.f32x2 %0, %1, %2, %3;" : "=l"(d) : "l"(a), "l"(b), "l"(c)); return d;
}
__device__ __forceinline__ ull add2(ull a, ull b) {
    ull d; asm("add.rn.f32x2 %0, %1, %2;" : "=l"(d) : "l"(a), "l"(b)); return d;
}
__device__ __forceinline__ ull mul2(ull a, ull b) {
    ull d; asm("mul.rn.f32x2 %0, %1, %2;" : "=l"(d) : "l"(a), "l"(b)); return d;
}

// Interleaved dd layout: half0 chunk m -> floats 8m+0..3, half1 chunk m -> 8m+4..7.
// A warp's two broadcast LDS.128 addresses are 16B apart inside one 32B window
// -> candidate single-wavefront service instead of two.
__device__ __forceinline__ int dd_slot(int j) {
    return (j < 64) ? (8 * (j >> 2) + (j & 3))
                    : (8 * ((j - 64) >> 2) + 4 + ((j - 64) & 3));
}

// One fused kernel, 288 threads:
//   warps 0-7 : row j = w*16+(l&15), half hf = l>>4; W half-row in registers
//               from Gauss-Jordan straight through the ADMM loop.
//   warp 8    : scalar equality row (32-lane shfl reduction, q permuted).
__global__ void __launch_bounds__(288, 1)
mvo_kernel(const float* __restrict__ X, const float* __restrict__ V,
           const float* __restrict__ beta, const float* __restrict__ thE,
           const float* __restrict__ thD, const float* __restrict__ lg1,
           const float* __restrict__ lg2, const float* __restrict__ bvec,
           const float* __restrict__ hvec, float* __restrict__ out) {
    __shared__ __align__(16) ull rowbuf[2][64];
    __shared__ __align__(16) float sddI[2][N];      // interleaved dd, double buffered
    __shared__ __align__(16) float sqI[N];          // q permuted into dd_slot order
    __shared__ float red8[8];
    __shared__ float sQ1;
    __shared__ float c2buf[2];
    __shared__ __align__(16) float sx[N];

    const int tid = threadIdx.x;
    const int b = blockIdx.x;
    const int w = tid >> 5, l = tid & 31;
    const bool rowt = (tid < 256);
    const int j = (w & 7) * 16 + (l & 15);
    const int hf = l >> 4;

    if (tid < 128) sx[tid] = X[b * N + tid];
    if (tid == 0) { c2buf[0] = 0.f; c2buf[1] = 0.f; }
    __syncthreads();

    // ---------- per-row constants + y_pred ----------
    float yp2 = 0.f, pt2 = 0.f, up1 = 0.f;
    ull rr[32];
    if (rowt) {
        float acc = 0.f;
        {
            const float* xp = sx + hf * 64;
            const float* bp = beta + (hf * 64) * N + j;
#pragma unroll 8
            for (int k = 0; k < 64; k++) acc = fmaf(xp[k], bp[k * N], acc);
        }
        float yp = acc + __shfl_xor_sync(0xffffffffu, acc, 16);
        if (hf == 0) out[BATCH * N + b * N + j] = yp;
        yp2 = 2.0f * yp;
        const float g1v = exp10f(lg1[0]);
        const float ev  = 1.0f / (1.0f + expf(-thE[j]));
        pt2 = 2.0f * (ALPHA * g1v * ev);
        up1 = hvec[j];

        const float g2 = exp10f(lg2[0]);
        const float sg = 1.0f / (1.0f + expf(-thD[j]));
        const float dg = 2.0f * (1.0f - ALPHA) * g2 * sg * sg + 3.0f * RHO + SIGMA;
        const float2* vrow = (const float2*)(V + j * N + hf * 64);
#pragma unroll
        for (int m = 0; m < 32; m++) {
            float2 v = vrow[m];
            float a = fmaf(2.0f * DELTA, v.x, 2.0f * RHO);
            float c = fmaf(2.0f * DELTA, v.y, 2.0f * RHO);
            int gc = hf * 64 + 2 * m;
            if (gc == j)     a += dg;
            if (gc + 1 == j) c += dg;
            rr[m] = pack2(a, c);
        }
    }

    // ---------- 128 Gauss-Jordan pivots (1 barrier each) ----------
#pragma unroll
    for (int k = 0; k < N; k++) {
        ull* buf = rowbuf[k & 1];
        if (rowt && j == k) {
            ulonglong2* buf2 = (ulonglong2*)buf;
#pragma unroll
            for (int m = 0; m < 16; m++)
                buf2[hf * 16 + m] = make_ulonglong2(rr[2 * m], rr[2 * m + 1]);
        }
        __syncthreads();
        if (rowt) {
            const float* bf = (const float*)buf;
            const float d = 1.0f / bf[k];
            const int mm = (k & 63) >> 1;
            F2U u; u.u = rr[mm];
            float fown = (k & 1) ? u.f.y : u.f.x;
            float f = __shfl_sync(0xffffffffu, fown, (l & 15) | ((k >> 6) << 4));
            const ulonglong2* bh = (const ulonglong2*)(buf + hf * 32);
            if (j == k) {
                ull d2 = pack2(d, d);
#pragma unroll
                for (int m = 0; m < 32; m++) rr[m] = mul2(rr[m], d2);
                if (hf == (k >> 6)) {
                    F2U t; t.u = rr[mm];
                    if (k & 1) t.f.y = d; else t.f.x = d;
                    rr[mm] = t.u;
                }
            } else {
                float fd = f * d;
                ull nf2 = pack2(-fd, -fd);
#pragma unroll
                for (int m = 0; m < 16; m++) {
                    ulonglong2 bb = bh[m];
                    rr[2 * m]     = fma2(nf2, bb.x, rr[2 * m]);
                    rr[2 * m + 1] = fma2(nf2, bb.y, rr[2 * m + 1]);
                }
                if (hf == (k >> 6)) {
                    F2U t; t.u = rr[mm];
                    if (k & 1) t.f.y = -fd; else t.f.x = -fd;
                    rr[mm] = t.u;
                }
            }
        }
    }

    // ---------- q = W@1, Q1 ----------
    float qj = 0.f;
    const int slot = dd_slot(j);
    if (rowt) {
        ull s0 = 0, s1 = 0, s2 = 0, s3 = 0;
#pragma unroll
        for (int m = 0; m < 32; m += 4) {
            s0 = add2(s0, rr[m]);     s1 = add2(s1, rr[m + 1]);
            s2 = add2(s2, rr[m + 2]); s3 = add2(s3, rr[m + 3]);
        }
        F2U ts; ts.u = add2(add2(s0, s1), add2(s2, s3));
        float qh = ts.f.x + ts.f.y;
        qj = qh + __shfl_xor_sync(0xffffffffu, qh, 16);
        if (hf == 0) sqI[slot] = qj;
        float r = qj;
        r += __shfl_xor_sync(0xffffffffu, r, 8);
        r += __shfl_xor_sync(0xffffffffu, r, 4);
        r += __shfl_xor_sync(0xffffffffu, r, 2);
        r += __shfl_xor_sync(0xffffffffu, r, 1);
        if (l == 0) red8[w] = r;
    }
    __syncthreads();
    if (tid == 0) {
        float t = 0.f;
#pragma unroll
        for (int i = 0; i < 8; i++) t += red8[i];
        sQ1 = t;
    }
    __syncthreads();

    const float omr = 1.0f - RELAX;
    const float half_inv_rs = 0.5f / (RHO + SIGMA);

    // ---------- 500-iteration ADMM ----------
    if (rowt) {
        const ull HALF2 = pack2(0.5f, -0.5f);
        const ull R2v   = pack2(RELAX, RELAX);
        const ull mR2   = pack2(-RELAX, -RELAX);
        const ull OMR2  = pack2(omr, omr);

        ull Xp = 0ull;                 // (x1, x2)
        ull V23 = 0ull;                // (v2, v3)
        float v1 = 0.f, z1 = 0.f;
        float ddl = yp2, s = -pt2;

#pragma unroll 2
        for (int it = 0; it < NITERS; it++) {
            const int p = it & 1;
            if (hf == 0) sddI[p][slot] = ddl;
            __syncthreads();
            const float c2 = c2buf[p];

            // interleaved half-row matvec: 16 LDS.128 + 32 f32x2 FMA
            const ulonglong2* dds = (const ulonglong2*)sddI[p];
            ull a0 = 0ull, a1 = 0ull, a2 = 0ull, a3 = 0ull;
#pragma unroll
            for (int m = 0; m < 8; m++) {
                ulonglong2 d0 = dds[4 * m + hf];
                ulonglong2 d1 = dds[4 * m + 2 + hf];
                a0 = fma2(rr[4 * m + 0], d0.x, a0);
                a1 = fma2(rr[4 * m + 1], d0.y, a1);
                a2 = fma2(rr[4 * m + 2], d1.x, a2);
                a3 = fma2(rr[4 * m + 3], d1.y, a3);
            }
            F2U acc; acc.u = add2(add2(a0, a1), add2(a2, a3));
            float th = acc.f.x + acc.f.y;
            float t = fmaf(c2, qj, th + __shfl_xor_sync(0xffffffffu, th, 16));

            // ---- slim epilogue (v-state form, f32x2-packed) ----
            float hsu = s * half_inv_rs;
            ull XT = fma2(HALF2, pack2(t, t), pack2(hsu, hsu));     // (xt1, xt2)
            Xp = fma2(R2v, XT, mul2(OMR2, Xp));                     // (x1, x2)

            float a1r = fmaf(-RELAX, z1, v1);
            v1 = fmaf(-RELAX, t, a1r);
            z1 = fminf(v1, up1);
            float u1 = fmaf(2.0f, z1, -v1);

            F2U vo; vo.u = V23;
            float a2r = fmaxf(vo.f.x, omr * vo.f.x);
            float a3r = fmaxf(vo.f.y, omr * vo.f.y);
            V23 = fma2(mR2, XT, pack2(a2r, a3r));
            F2U vn; vn.u = V23;
            float av2 = fabsf(vn.f.x);
            float av3 = fabsf(vn.f.y);

            F2U xu; xu.u = Xp;
            float dx  = xu.f.x - xu.f.y;
            float sxx = xu.f.x + xu.f.y;
            ddl = fmaf(SIGMA, dx, yp2);
            ddl = fmaf(-2.0f * RHO, u1, ddl);
            ddl = fmaf(RHO, av2, ddl);
            ddl = fmaf(-RHO, av3, ddl);
            s = fmaf(SIGMA, sxx, -pt2);
            s = fmaf(RHO, av2, s);
            s = fmaf(RHO, av3, s);
        }
        if (hf == 0) {
            F2U xu; xu.u = Xp;
            out[b * N + j] = xu.f.x - xu.f.y;
        }
    } else {
        // warp 8: scalar equality row, 32-lane shfl reduction (q permuted to match dd)
        float4 qa = ((const float4*)sqI)[l];
        float Q1v = sQ1;
        float b0 = bvec[0];
        float c2 = 0.f, Y0 = 0.f, z0 = 0.f;
#pragma unroll 2
        for (int it = 0; it < NITERS; it++) {
            const int p = it & 1;
            __syncthreads();
            float4 da = ((const float4*)sddI[p])[l];
            float r = qa.x * da.x + qa.y * da.y + qa.z * da.z + qa.w * da.w;
            r += __shfl_xor_sync(0xffffffffu, r, 16);
            r += __shfl_xor_sync(0xffffffffu, r, 8);
            r += __shfl_xor_sync(0xffffffffu, r, 4);
            r += __shfl_xor_sync(0xffffffffu, r, 2);
            r += __shfl_xor_sync(0xffffffffu, r, 1);
            float zt0 = fmaf(c2, Q1v, r);
            float zr0 = fmaf(omr, z0, RELAX * zt0);
            Y0 = Y0 + zr0 - b0;
            z0 = b0;
            c2 = 2.0f * RHO * (b0 - Y0);
            if (l == 0) c2buf[p ^ 1] = c2;
        }
    }
}

// ---------------- launcher ----------------
extern "C" void kernel_launch(void* const* d_in, const int* in_sizes, int n_in,
                              void* d_out, int out_size) {
    const float* X    = (const float*)d_in[0];
    const float* V    = (const float*)d_in[1];
    const float* beta = (const float*)d_in[2];
    const float* thE  = (const float*)d_in[3];
    const float* thD  = (const float*)d_in[4];
    const float* lg1  = (const float*)d_in[5];
    const float* lg2  = (const float*)d_in[6];
    const float* bvec = (const float*)d_in[8];
    const float* hvec = (const float*)d_in[10];
    float* out = (float*)d_out;

    mvo_kernel<<<BATCH, 288>>>(X, V, beta, thE, thD, lg1, lg2, bvec, hvec, out);
}